// round 7
// baseline (speedup 1.0000x reference)
#include <cuda_runtime.h>
#include <cuda_bf16.h>

#define V_DIM 32
#define NB 14          // N_BASIS
#define NP 496         // V*(V-1)/2
#define PSTRIDE 512    // padded params row stride (conflict-free)
#define NW 16          // warps per block
#define NTHREADS 512
#define GRID 296       // 2 blocks/SM

struct __align__(16) WarpScratch {
    float Ls[V_DIM * V_DIM];  // exact lm-row image [32][32]; diag/upper set once
};

struct SmemLayout {
    float P[NB * PSTRIDE];    // staged padded params (28672 B)
    WarpScratch w[NW];        // 4 KB per warp
    float red[3][NW];
};

__device__ __forceinline__ unsigned smem_u32(const void* p) {
    return (unsigned)__cvta_generic_to_shared(p);
}

__global__ __launch_bounds__(NTHREADS, 2)
void decor_kernel(const float* __restrict__ input,
                  const float* __restrict__ params,
                  float* __restrict__ d_out,
                  float* __restrict__ scal,
                  int n)
{
    extern __shared__ char smem_raw[];
    SmemLayout* S = reinterpret_cast<SmemLayout*>(smem_raw);

    const int tid  = threadIdx.x;
    const int warp = tid >> 5;
    const int lane = tid & 31;

    // ---- stage params (padded) once per block ----
    for (int i = tid; i < NB * NP; i += NTHREADS) {
        int r = i / NP, cc = i - r * NP;
        S->P[r * PSTRIDE + cc] = params[i];
    }

    WarpScratch* W = &S->w[warp];
    const unsigned ls_smem = smem_u32(W->Ls);

    // one-time Ls image init: identity diag, zero elsewhere
    // (lam overwrites exactly the strict-lower 496 slots every row)
    for (int idx = lane; idx < V_DIM * V_DIM; idx += 32) {
        int r = idx >> 5, cc = idx & 31;
        W->Ls[idx] = (r == cc) ? 1.0f : 0.0f;
    }

    // row-independent pair geometry: p = lane+32*i -> (v, pb) packed
    int K[16];
    #pragma unroll
    for (int i = 0; i < 16; i++) {
        int p = lane + 32 * i;
        int v = (int)((1.0f + sqrtf(8.0f * (float)p + 1.0f)) * 0.5f);
        while (v * (v + 1) / 2 <= p) v++;
        while (v * (v - 1) / 2 > p) v--;
        K[i] = (v << 16) | (v * (v - 1) / 2);
    }
    __syncthreads();

    // ---- block 0: fused penalties ----
    if (blockIdx.x == 0) {
        float s0 = 0.f, s1 = 0.f, s2 = 0.f;
        for (int i = tid; i < NB * NP; i += NTHREADS) {
            int k = i / NP, cc = i - k * NP;
            float p0 = S->P[k * PSTRIDE + cc];
            s0 += p0 * p0;
            if (k < NB - 1) {
                float p1 = S->P[(k + 1) * PSTRIDE + cc];
                float a = p1 - p0;
                s1 += a * a;
                if (k < NB - 2) {
                    float b = S->P[(k + 2) * PSTRIDE + cc] - 2.0f * p1 + p0;
                    s2 += b * b;
                }
            }
        }
        #pragma unroll
        for (int off = 16; off > 0; off >>= 1) {
            s0 += __shfl_down_sync(0xffffffffu, s0, off);
            s1 += __shfl_down_sync(0xffffffffu, s1, off);
            s2 += __shfl_down_sync(0xffffffffu, s2, off);
        }
        if (lane == 0) { S->red[0][warp] = s2; S->red[1][warp] = s1; S->red[2][warp] = s0; }
        __syncthreads();
        if (tid < 3) {
            float t = 0.f;
            #pragma unroll
            for (int w2 = 0; w2 < NW; w2++) t += S->red[tid][w2];
            scal[tid] = t;   // [0]=second, [1]=first, [2]=param
        }
    }

    const float LOv = -15.0f, HIv = 15.0f;
    const float inv_dist = 11.0f / 30.0f;

    float* lm = d_out + (size_t)n * V_DIM;
    const int row_stride = gridDim.x * NW;

    for (int row = blockIdx.x * NW + warp; row < n; row += row_stride) {

        // input row: lane owns column `lane`
        float xi = input[(size_t)row * V_DIM + lane];

        // basis for column c = lane, in registers
        float b0, b1, b2, b3;
        int   pt;
        {
            float xc = fminf(fmaxf(xi, LOv), HIv - 1e-6f);
            float s  = (xc - LOv) * inv_dist;       // [0, 11)
            int j0 = min((int)s, 10);
            float u  = s - (float)j0;
            float um = 1.0f - u;
            float u2 = u * u, u3 = u2 * u;
            b0 = um * um * um * (1.0f / 6.0f);
            b1 = (3.0f * u3 - 6.0f * u2 + 4.0f) * (1.0f / 6.0f);
            b2 = (-3.0f * u3 + 3.0f * u2 + 3.0f * u + 1.0f) * (1.0f / 6.0f);
            b3 = u3 * (1.0f / 6.0f);
            pt = j0 * PSTRIDE;
        }

        // previous row's bulk store must have READ our smem image before we
        // overwrite it (first iteration: no pending groups, no-op)
        if (lane == 0)
            asm volatile("cp.async.bulk.wait_group.read 0;" ::: "memory");
        __syncwarp();

        // lam: dense p-linear lanes; basis via indexed shuffle;
        // P conflict-free (PSTRIDE%32==0); scatter into row image
        #pragma unroll
        for (int i = 0; i < 16; i++) {
            int p  = lane + 32 * i;
            int kk = K[i];
            int v  = kk >> 16;
            int c  = (p - (kk & 0xFFFF)) & 31;
            float c0 = __shfl_sync(0xffffffffu, b0, c);
            float c1 = __shfl_sync(0xffffffffu, b1, c);
            float c2 = __shfl_sync(0xffffffffu, b2, c);
            float c3 = __shfl_sync(0xffffffffu, b3, c);
            int   cp = __shfl_sync(0xffffffffu, pt, c);
            const float* Pp = S->P + cp + p;
            float l = c0 * Pp[0];
            l = fmaf(c1, Pp[PSTRIDE],     l);
            l = fmaf(c2, Pp[2 * PSTRIDE], l);
            l = fmaf(c3, Pp[3 * PSTRIDE], l);
            if (p < NP) W->Ls[(v << 5) + c] = l;
        }
        __syncwarp();

        // one async bulk store ships the whole 4 KB lm row (replaces 8 STG.128)
        if (lane == 0) {
            asm volatile("fence.proxy.async.shared::cta;" ::: "memory");
            asm volatile(
                "cp.async.bulk.global.shared::cta.bulk_group [%0], [%1], %2;"
                :: "l"(lm + (size_t)row * (V_DIM * V_DIM)), "r"(ls_smem),
                   "n"(V_DIM * V_DIM * 4)
                : "memory");
            asm volatile("cp.async.bulk.commit_group;" ::: "memory");
        }

        // out[v] = dot(lm_row_v, x): rotated reads -> bank (v+c)%32, conflict-free
        {
            float acc = 0.0f;
            #pragma unroll
            for (int c = 0; c < V_DIM; c++) {
                int col = (lane + c) & 31;
                float lv = W->Ls[(lane << 5) + col];
                float xc = __shfl_sync(0xffffffffu, xi, col);
                acc = fmaf(lv, xc, acc);
            }
            d_out[(size_t)row * V_DIM + lane] = acc;
        }
        // NOTE: no extra syncwarp needed; next iteration's wait_group +
        // syncwarp guards the smem image before the next scatter.
    }

    // drain outstanding bulk stores before exit
    if (lane == 0)
        asm volatile("cp.async.bulk.wait_group 0;" ::: "memory");
}

extern "C" void kernel_launch(void* const* d_in, const int* in_sizes, int n_in,
                              void* d_out, int out_size)
{
    const float* input  = (const float*)d_in[0];
    // d_in[1] = log_d (unused by the reference's outputs)
    const float* params = (const float*)d_in[2];
    float* outp = (float*)d_out;
    int n = in_sizes[0] / V_DIM;

    float* scal = outp + (size_t)n * V_DIM + (size_t)n * V_DIM * V_DIM;

    size_t smem = sizeof(SmemLayout);
    cudaFuncSetAttribute(decor_kernel, cudaFuncAttributeMaxDynamicSharedMemorySize, (int)smem);

    decor_kernel<<<GRID, NTHREADS, smem>>>(input, params, outp, scal, n);
}

// round 8
// speedup vs baseline: 1.2948x; 1.2948x over previous
#include <cuda_runtime.h>
#include <cuda_bf16.h>

#define V_DIM 32
#define NB 14          // N_BASIS
#define NP 496         // V*(V-1)/2
#define PSTRIDE 512    // padded params row stride: bank-conflict-free (512%32==0)
#define NW 16          // warps per block
#define NTHREADS 512
#define GRID 296       // 2 blocks/SM on 148 SMs

struct WarpScratch {
    float Ls[NP];          // lam values, p-linear (conflict-free STS)
    float Od[V_DIM];       // out staging
};

struct SmemLayout {
    float P[NB * PSTRIDE]; // padded staged params (28672 B)
    WarpScratch w[NW];
    float red[3][NW];
};

__global__ __launch_bounds__(NTHREADS, 2)
void decor_kernel(const float* __restrict__ input,
                  const float* __restrict__ params,
                  float* __restrict__ d_out,
                  float* __restrict__ scal,
                  int n)
{
    extern __shared__ char smem_raw[];
    SmemLayout* S = reinterpret_cast<SmemLayout*>(smem_raw);

    const int tid  = threadIdx.x;
    const int warp = tid >> 5;
    const int lane = tid & 31;

    // ---- stage params (padded) once per block ----
    for (int i = tid; i < NB * NP; i += NTHREADS) {
        int r = i / NP, cc = i - r * NP;
        S->P[r * PSTRIDE + cc] = params[i];
    }

    WarpScratch* W = &S->w[warp];

    // row-independent pair geometry: p = lane+32*i -> pb = v(v-1)/2
    int PB[16];
    #pragma unroll
    for (int i = 0; i < 16; i++) {
        int p = lane + 32 * i;
        int v = (int)((1.0f + sqrtf(8.0f * (float)p + 1.0f)) * 0.5f);
        while (v * (v + 1) / 2 <= p) v++;
        while (v * (v - 1) / 2 > p) v--;
        PB[i] = v * (v - 1) / 2;
    }
    __syncthreads();

    // ---- block 0: fused penalties ----
    if (blockIdx.x == 0) {
        float s0 = 0.f, s1 = 0.f, s2 = 0.f;
        for (int i = tid; i < NB * NP; i += NTHREADS) {
            int k = i / NP, cc = i - k * NP;
            float p0 = S->P[k * PSTRIDE + cc];
            s0 += p0 * p0;
            if (k < NB - 1) {
                float p1 = S->P[(k + 1) * PSTRIDE + cc];
                float a = p1 - p0;
                s1 += a * a;
                if (k < NB - 2) {
                    float b = S->P[(k + 2) * PSTRIDE + cc] - 2.0f * p1 + p0;
                    s2 += b * b;
                }
            }
        }
        #pragma unroll
        for (int off = 16; off > 0; off >>= 1) {
            s0 += __shfl_down_sync(0xffffffffu, s0, off);
            s1 += __shfl_down_sync(0xffffffffu, s1, off);
            s2 += __shfl_down_sync(0xffffffffu, s2, off);
        }
        if (lane == 0) { S->red[0][warp] = s2; S->red[1][warp] = s1; S->red[2][warp] = s0; }
        __syncthreads();
        if (tid < 3) {
            float t = 0.f;
            #pragma unroll
            for (int w2 = 0; w2 < NW; w2++) t += S->red[tid][w2];
            scal[tid] = t;   // [0]=second, [1]=first, [2]=param
        }
    }

    const float LOv = -15.0f, HIv = 15.0f;
    const float inv_dist = 11.0f / 30.0f;

    float* lm = d_out + (size_t)n * V_DIM;
    const int row_stride = gridDim.x * NW;

    for (int row = blockIdx.x * NW + warp; row < n; row += row_stride) {

        // input row: lane owns column `lane` (coalesced LDG)
        float xi = input[(size_t)row * V_DIM + lane];

        // x segment for the fused dot: lane-constant across store iters
        const int cb = (lane & 7) << 2;
        float xq0 = __shfl_sync(0xffffffffu, xi, cb);
        float xq1 = __shfl_sync(0xffffffffu, xi, cb + 1);
        float xq2 = __shfl_sync(0xffffffffu, xi, cb + 2);
        float xq3 = __shfl_sync(0xffffffffu, xi, cb + 3);

        // lam: 1 shuffle of raw x + in-lane basis recompute (no gather),
        // P loads conflict-free (PSTRIDE%32==0), Ls p-linear STS
        #pragma unroll
        for (int i = 0; i < 16; i++) {
            int p = lane + 32 * i;
            int c = (p - PB[i]) & 31;
            float xc = __shfl_sync(0xffffffffu, xi, c);
            xc = fminf(fmaxf(xc, LOv), HIv - 1e-6f);
            float s  = (xc - LOv) * inv_dist;       // [0, 11)
            int j0 = min((int)s, 10);
            float u  = s - (float)j0;
            float um = 1.0f - u;
            float u2 = u * u, u3 = u2 * u;
            float c0 = um * um * um * (1.0f / 6.0f);
            float c1 = (3.0f * u3 - 6.0f * u2 + 4.0f) * (1.0f / 6.0f);
            float c2 = (-3.0f * u3 + 3.0f * u2 + 3.0f * u + 1.0f) * (1.0f / 6.0f);
            float c3 = u3 * (1.0f / 6.0f);
            const float* Pp = S->P + j0 * PSTRIDE + p;
            float l = c0 * Pp[0];
            l = fmaf(c1, Pp[PSTRIDE],     l);
            l = fmaf(c2, Pp[2 * PSTRIDE], l);
            l = fmaf(c3, Pp[3 * PSTRIDE], l);
            if (p < NP) W->Ls[p] = l;
        }
        __syncwarp();

        // lm store (STG.128, coalesced) with fused out = lm @ x
        float4* lmrow = reinterpret_cast<float4*>(lm + (size_t)row * V_DIM * V_DIM);
        #pragma unroll
        for (int i = 0; i < 8; i++) {
            int t4 = lane + 32 * i;          // == v*8 + c0/4
            int v  = t4 >> 3;
            int pb = (v * (v - 1)) >> 1;
            float vals[4];
            #pragma unroll
            for (int q = 0; q < 4; q++) {
                int c = cb + q;
                float val = 0.0f;
                if (c < v)       val = W->Ls[pb + c];
                else if (c == v) val = 1.0f;
                vals[q] = val;
            }
            __stcs(&lmrow[t4], make_float4(vals[0], vals[1], vals[2], vals[3]));

            float dv = vals[0] * xq0;
            dv = fmaf(vals[1], xq1, dv);
            dv = fmaf(vals[2], xq2, dv);
            dv = fmaf(vals[3], xq3, dv);
            dv += __shfl_xor_sync(0xffffffffu, dv, 4, 8);
            dv += __shfl_xor_sync(0xffffffffu, dv, 2, 8);
            dv += __shfl_xor_sync(0xffffffffu, dv, 1, 8);
            if ((lane & 7) == 0) W->Od[v] = dv;
        }
        __syncwarp();

        // coalesced out-row store
        d_out[(size_t)row * V_DIM + lane] = W->Od[lane];

        __syncwarp();   // protect scratch before next row
    }
}

extern "C" void kernel_launch(void* const* d_in, const int* in_sizes, int n_in,
                              void* d_out, int out_size)
{
    const float* input  = (const float*)d_in[0];
    // d_in[1] = log_d (unused by the reference's outputs)
    const float* params = (const float*)d_in[2];
    float* outp = (float*)d_out;
    int n = in_sizes[0] / V_DIM;

    float* scal = outp + (size_t)n * V_DIM + (size_t)n * V_DIM * V_DIM;

    size_t smem = sizeof(SmemLayout);
    cudaFuncSetAttribute(decor_kernel, cudaFuncAttributeMaxDynamicSharedMemorySize, (int)smem);

    decor_kernel<<<GRID, NTHREADS, smem>>>(input, params, outp, scal, n);
}